// round 6
// baseline (speedup 1.0000x reference)
#include <cuda_runtime.h>

#define KC    9
#define TPB   256
#define ROWS  3
#define TILE  (TPB * ROWS)   // 768 rows per block, smem 27648 B -> 8 CTA/SM

__device__ float         g_partials[65536];
__device__ unsigned int  g_counter = 0;

__device__ __forceinline__ float warp_reduce(float v) {
#pragma unroll
    for (int o = 16; o; o >>= 1) v += __shfl_xor_sync(0xffffffffu, v, o);
    return v;
}

__global__ void __launch_bounds__(TPB, 8)
ordinal_loss_fused(const float* __restrict__ logits,
                   const int*   __restrict__ y,
                   float*       __restrict__ out,
                   int B, int nblocks) {
    __shared__ float sl[TILE * KC];          // 27648 B staging
    __shared__ float ws[TPB / 32];
    __shared__ bool  s_last;

    const int row0  = blockIdx.x * TILE;
    const int nrows = min(TILE, B - row0);

    // ---- stage logits (coalesced 16B streaming loads; 768*9*4 % 16 == 0) ----
    if (nrows == TILE) {
        const float4* src = reinterpret_cast<const float4*>(logits + (size_t)row0 * KC);
        float4*       dst = reinterpret_cast<float4*>(sl);
        for (int j = threadIdx.x; j < TILE * KC / 4; j += TPB)
            dst[j] = __ldcs(&src[j]);
    } else {
        for (int j = threadIdx.x; j < nrows * KC; j += TPB)
            sl[j] = logits[(size_t)row0 * KC + j];
    }
    __syncthreads();

    float contrib = 0.0f;

#pragma unroll
    for (int j = 0; j < ROWS; j++) {
        const int r = threadIdx.x + j * TPB;             // stride-9 smem: conflict-free
        if (r < nrows) {
            const int   yy   = y[row0 + r];
            const int   base = r * KC;
            const float yf   = (float)yy;

            // dynamic neighbor loads issued early (latency overlapped with loop)
            const float ly = sl[base + yy];
            const float ll = sl[base + ((yy > 0)      ? yy - 1 : 0)];
            const float lr = sl[base + ((yy < KC - 1) ? yy + 1 : KC - 1)];

            // single fused pass: exp, running cdf c, tail, far, and EMD moments
            //   emd2*Z^2 = A - 2 Z B + Z^2 W,  A=Σw c², B=Σw t c, W=Σw t, t=sat(1-d)
            float run = 0.0f, tail_e = 0.0f, far_e = 0.0f;
            float A = 0.0f, Bm = 0.0f, W = 0.0f;
#pragma unroll
            for (int k = 0; k < KC; k++) {
                const float ek = __expf(sl[base + k]);
                run += ek;
                const float c  = run;
                const float d  = (float)k - yf;
                const float f1 = fmaxf(fabsf(d) - 1.0f, 0.0f);
                const float g  = fminf(f1, 1.0f);
                tail_e = fmaf(ek, f1 * f1 * f1, tail_e);
                far_e  = fmaxf(far_e, ek * g);

                const float t  = __saturatef(1.0f - d);
                const float w  = (k == 0) ? 3.0f/95.0f : (k == 1) ? 7.0f/95.0f
                               : (k == KC-1) ? 25.0f/95.0f : 10.0f/95.0f;
                const float wt = w * t;
                A  = fmaf(w * c, c, A);
                Bm = fmaf(wt, c, Bm);
                W += wt;
            }

            const float Z   = run;
            const float rZ  = __fdividef(1.0f, Z);
            const float rZ2 = rZ * rZ;
            const float nll = __logf(Z) - ly;

            const float py_e = __expf(ly);
            const float pl_e = (yy > 0)      ? __expf(ll) : 0.0f;
            const float pr_e = (yy < KC - 1) ? __expf(lr) : 0.0f;

            const float emd2 = fmaf(Z, fmaf(Z, W, -2.0f * Bm), A) * rZ2;
            const float py   = py_e * rZ;
            const float far_margin = fmaxf(fmaf(far_e, rZ, 0.15f - py), 0.0f);
            const float local_peak = fmaxf(fmaf(fmaxf(pl_e, pr_e), rZ, 0.35f - py), 0.0f);

            contrib += nll * 0.45511961331341866f        // 1/ln(9)
                     + 0.4f * (7.0f * far_margin + 9.0f * (tail_e * rZ)
                             + 12.0f * local_peak + 1.2f * emd2);
        }
    }

    // ---- block reduction ----
    contrib = warp_reduce(contrib);
    if ((threadIdx.x & 31) == 0) ws[threadIdx.x >> 5] = contrib;
    __syncthreads();
    if (threadIdx.x < 32) {
        float v = (threadIdx.x < TPB / 32) ? ws[threadIdx.x] : 0.0f;
        v = warp_reduce(v);
        if (threadIdx.x == 0) {
            g_partials[blockIdx.x] = v;
            __threadfence();
            unsigned int t = atomicAdd(&g_counter, 1u);
            s_last = (t == (unsigned int)(nblocks - 1));
        }
    }
    __syncthreads();

    // ---- last arriving block: deterministic fixed-order final sum ----
    if (s_last) {
        float v = 0.0f;
        for (int i = threadIdx.x; i < nblocks; i += TPB) v += g_partials[i];
        v = warp_reduce(v);
        if ((threadIdx.x & 31) == 0) ws[threadIdx.x >> 5] = v;
        __syncthreads();
        if (threadIdx.x < 32) {
            float t = (threadIdx.x < TPB / 32) ? ws[threadIdx.x] : 0.0f;
            t = warp_reduce(t);
            if (threadIdx.x == 0) {
                out[0] = t / (float)B;
                g_counter = 0;                 // re-arm for next graph replay
            }
        }
    }
}

extern "C" void kernel_launch(void* const* d_in, const int* in_sizes, int n_in,
                              void* d_out, int out_size) {
    const float* logits = (const float*)d_in[0];
    const int*   y      = (const int*)d_in[1];
    const int    B      = in_sizes[1];

    const int nblocks = (B + TILE - 1) / TILE;     // 5462 for B = 4,194,304

    ordinal_loss_fused<<<nblocks, TPB>>>(logits, y, (float*)d_out, B, nblocks);
}

// round 7
// speedup vs baseline: 1.6742x; 1.6742x over previous
#include <cuda_runtime.h>

#define KC    9
#define TPB   128
#define ROWS  3
#define TILE  (TPB * ROWS)   // 384 rows/block, smem ~13.9KB -> 16 CTA/SM

__device__ float         g_partials[65536];
__device__ unsigned int  g_counter = 0;

__device__ __forceinline__ float warp_reduce(float v) {
#pragma unroll
    for (int o = 16; o; o >>= 1) v += __shfl_xor_sync(0xffffffffu, v, o);
    return v;
}

__global__ void __launch_bounds__(TPB)
ordinal_loss_fused(const float* __restrict__ logits,
                   const int*   __restrict__ y,
                   float*       __restrict__ out,
                   int B, int nblocks) {
    __shared__ float sl[TILE * KC];          // 13824 B staging
    __shared__ float ws[TPB / 32];
    __shared__ bool  s_last;

    const int row0  = blockIdx.x * TILE;
    const int nrows = min(TILE, B - row0);

    // ---- stage logits (coalesced 16B streaming loads; 384*9*4 % 16 == 0) ----
    if (nrows == TILE) {
        const float4* src = reinterpret_cast<const float4*>(logits + (size_t)row0 * KC);
        float4*       dst = reinterpret_cast<float4*>(sl);
        for (int j = threadIdx.x; j < TILE * KC / 4; j += TPB)
            dst[j] = __ldcs(&src[j]);
    } else {
        for (int j = threadIdx.x; j < nrows * KC; j += TPB)
            sl[j] = logits[(size_t)row0 * KC + j];
    }
    __syncthreads();

    float contrib = 0.0f;

#pragma unroll
    for (int j = 0; j < ROWS; j++) {
        const int r = threadIdx.x + j * TPB;             // stride-9 smem: conflict-free
        if (r < nrows) {
            const int   yy   = y[row0 + r];
            const int   base = r * KC;
            const float yf   = (float)yy;

            // exp + running cdf (Z = cdf[last])
            float e[KC], cdf[KC];
            float run = 0.0f;
#pragma unroll
            for (int k = 0; k < KC; k++) {
                e[k] = __expf(sl[base + k]);
                run += e[k];
                cdf[k] = run;
            }
            const float Z  = run;
            const float rZ = __fdividef(1.0f, Z);

            // target / neighbor probs via direct dynamic smem loads (only 3)
            const float ly   = sl[base + yy];
            const float py_e = __expf(ly);
            const float pl_e = (yy > 0)      ? __expf(sl[base + yy - 1]) : 0.0f;
            const float pr_e = (yy < KC - 1) ? __expf(sl[base + yy + 1]) : 0.0f;

            const float nll = __logf(Z) - ly;

            // select-free FMA-pipe pass
            float far_e = 0.0f, tail_e = 0.0f, emd2 = 0.0f;
#pragma unroll
            for (int k = 0; k < KC; k++) {
                const float ad = fabsf((float)k - yf);
                const float f1 = fmaxf(ad - 1.0f, 0.0f);
                const float g  = fminf(f1, 1.0f);
                tail_e = fmaf(e[k], f1 * f1 * f1, tail_e);
                far_e  = fmaxf(far_e, e[k] * g);

                const float t  = __saturatef(yf - (float)(k - 1));
                const float df = fmaf(cdf[k], rZ, -t);
                const float w  = (k == 0) ? 3.0f/95.0f : (k == 1) ? 7.0f/95.0f
                               : (k == KC-1) ? 25.0f/95.0f : 10.0f/95.0f;
                emd2 = fmaf(df * df, w, emd2);
            }

            const float py = py_e * rZ;
            const float far_margin = fmaxf(fmaf(far_e, rZ, 0.15f - py), 0.0f);
            const float local_peak = fmaxf(fmaf(fmaxf(pl_e, pr_e), rZ, 0.35f - py), 0.0f);

            contrib += nll * 0.45511961331341866f        // 1/ln(9)
                     + 0.4f * (7.0f * far_margin + 9.0f * (tail_e * rZ)
                             + 12.0f * local_peak + 1.2f * emd2);
        }
    }

    // ---- block reduction ----
    contrib = warp_reduce(contrib);
    if ((threadIdx.x & 31) == 0) ws[threadIdx.x >> 5] = contrib;
    __syncthreads();
    if (threadIdx.x < 32) {
        float v = (threadIdx.x < TPB / 32) ? ws[threadIdx.x] : 0.0f;
        v = warp_reduce(v);
        if (threadIdx.x == 0) {
            g_partials[blockIdx.x] = v;
            __threadfence();
            unsigned int t = atomicAdd(&g_counter, 1u);
            s_last = (t == (unsigned int)(nblocks - 1));
        }
    }
    __syncthreads();

    // ---- last arriving block: deterministic fixed-order final sum ----
    if (s_last) {
        float v = 0.0f;
        for (int i = threadIdx.x; i < nblocks; i += TPB) v += g_partials[i];
        v = warp_reduce(v);
        if ((threadIdx.x & 31) == 0) ws[threadIdx.x >> 5] = v;
        __syncthreads();
        if (threadIdx.x < 32) {
            float t = (threadIdx.x < TPB / 32) ? ws[threadIdx.x] : 0.0f;
            t = warp_reduce(t);
            if (threadIdx.x == 0) {
                out[0] = t / (float)B;
                g_counter = 0;                 // re-arm for next graph replay
            }
        }
    }
}

extern "C" void kernel_launch(void* const* d_in, const int* in_sizes, int n_in,
                              void* d_out, int out_size) {
    const float* logits = (const float*)d_in[0];
    const int*   y      = (const int*)d_in[1];
    const int    B      = in_sizes[1];

    const int nblocks = (B + TILE - 1) / TILE;     // 10923 for B = 4,194,304

    ordinal_loss_fused<<<nblocks, TPB>>>(logits, y, (float*)d_out, B, nblocks);
}

// round 8
// speedup vs baseline: 2.0365x; 1.2164x over previous
#include <cuda_runtime.h>

#define KC    9
#define TPB   256
#define ROWS  4
#define TILE  (TPB * ROWS)   // 1024 rows per block (R4-winning shape)

#define LOG2E 1.4426950408889634f
#define LN2_OVER_LN9 0.31546487678572877f   // ln2/ln9

__device__ float         g_partials[65536];
__device__ unsigned int  g_counter = 0;

__device__ __forceinline__ float warp_reduce(float v) {
#pragma unroll
    for (int o = 16; o; o >>= 1) v += __shfl_xor_sync(0xffffffffu, v, o);
    return v;
}

__device__ __forceinline__ float ex2(float x) {
    float r;
    asm("ex2.approx.f32 %0, %1;" : "=f"(r) : "f"(x));
    return r;
}
__device__ __forceinline__ float lg2(float x) {
    float r;
    asm("lg2.approx.f32 %0, %1;" : "=f"(r) : "f"(x));
    return r;
}

__global__ void __launch_bounds__(TPB)
ordinal_loss_fused(const float* __restrict__ logits,
                   const int*   __restrict__ y,
                   float*       __restrict__ out,
                   int B, int nblocks) {
    __shared__ float sl[TILE * KC];          // 36864 B: logits pre-scaled by log2(e)
    __shared__ float tw[KC * KC];            // tail weights (|k-y|-1)^3, 324 B
    __shared__ float ws[TPB / 32];
    __shared__ bool  s_last;

    // ---- build tail-weight table ----
    if (threadIdx.x < KC * KC) {
        const int yy = threadIdx.x / KC;
        const int k  = threadIdx.x - yy * KC;
        const int ad = (k > yy) ? (k - yy) : (yy - k);
        const float f1 = (ad > 1) ? (float)(ad - 1) : 0.0f;
        tw[threadIdx.x] = f1 * f1 * f1;
    }

    const int row0  = blockIdx.x * TILE;
    const int nrows = min(TILE, B - row0);

    // ---- stage logits * log2e (coalesced 16B streaming loads) ----
    if (nrows == TILE) {
        const float4* src = reinterpret_cast<const float4*>(logits + (size_t)row0 * KC);
        float4*       dst = reinterpret_cast<float4*>(sl);
#pragma unroll
        for (int j = 0; j < TILE * KC / 4 / TPB; j++) {
            float4 v = __ldcs(&src[threadIdx.x + j * TPB]);
            v.x *= LOG2E; v.y *= LOG2E; v.z *= LOG2E; v.w *= LOG2E;
            dst[threadIdx.x + j * TPB] = v;
        }
    } else {
        for (int j = threadIdx.x; j < nrows * KC; j += TPB)
            sl[j] = logits[(size_t)row0 * KC + j] * LOG2E;
    }
    __syncthreads();

    float contrib = 0.0f;

#pragma unroll
    for (int j = 0; j < ROWS; j++) {
        const int r = threadIdx.x + j * TPB;             // stride-9 smem: conflict-free
        if (r < nrows) {
            const int   yy   = y[row0 + r];
            const int   base = r * KC;
            const float yf   = (float)yy;

            // exp pass: bare EX2 (logits pre-scaled), running cdf
            float e[KC], cdf[KC];
            float run = 0.0f;
#pragma unroll
            for (int k = 0; k < KC; k++) {
                e[k] = ex2(sl[base + k]);
                run += e[k];
                cdf[k] = run;
            }
            const float Z  = run;
            const float rZ = __fdividef(1.0f, Z);

            // target / neighbor probs via dynamic smem loads (bank-analysis safe)
            const float ly   = sl[base + yy];             // scaled logit
            const float py_e = ex2(ly);
            const float pl_e = (yy > 0)      ? ex2(sl[base + yy - 1]) : 0.0f;
            const float pr_e = (yy < KC - 1) ? ex2(sl[base + yy + 1]) : 0.0f;

            const float nll_lg2 = lg2(Z) - ly;            // nll / ln2

            // main pass: table tw + derived far mask; EMD in Z-form (no rZ in loop)
            const float* twr = &tw[yy * KC];
            float far_e = 0.0f, tail_e = 0.0f, emd_z = 0.0f;
#pragma unroll
            for (int k = 0; k < KC; k++) {
                const float twk = twr[k];                 // LDS.32, conflict-free
                tail_e = fmaf(e[k], twk, tail_e);
                const float g = fminf(twk, 1.0f);         // far mask
                far_e = fmaxf(far_e, e[k] * g);

                const float t  = __saturatef(yf - (float)(k - 1));  // cdf_true
                const float df = fmaf(-Z, t, cdf[k]);     // (cdf - t*Z)
                const float w  = (k == 0) ? 3.0f/95.0f : (k == 1) ? 7.0f/95.0f
                               : (k == KC-1) ? 25.0f/95.0f : 10.0f/95.0f;
                emd_z = fmaf(df * df, w, emd_z);
            }

            const float py   = py_e * rZ;
            const float emd2 = emd_z * rZ * rZ;
            const float far_margin = fmaxf(fmaf(far_e, rZ, 0.15f - py), 0.0f);
            const float local_peak = fmaxf(fmaf(fmaxf(pl_e, pr_e), rZ, 0.35f - py), 0.0f);

            contrib += nll_lg2 * LN2_OVER_LN9
                     + 0.4f * (7.0f * far_margin + 9.0f * (tail_e * rZ)
                             + 12.0f * local_peak + 1.2f * emd2);
        }
    }

    // ---- block reduction ----
    contrib = warp_reduce(contrib);
    if ((threadIdx.x & 31) == 0) ws[threadIdx.x >> 5] = contrib;
    __syncthreads();
    if (threadIdx.x < 32) {
        float v = (threadIdx.x < TPB / 32) ? ws[threadIdx.x] : 0.0f;
        v = warp_reduce(v);
        if (threadIdx.x == 0) {
            g_partials[blockIdx.x] = v;
            __threadfence();
            unsigned int t = atomicAdd(&g_counter, 1u);
            s_last = (t == (unsigned int)(nblocks - 1));
        }
    }
    __syncthreads();

    // ---- last arriving block: deterministic fixed-order final sum ----
    if (s_last) {
        float v = 0.0f;
        for (int i = threadIdx.x; i < nblocks; i += TPB) v += g_partials[i];
        v = warp_reduce(v);
        if ((threadIdx.x & 31) == 0) ws[threadIdx.x >> 5] = v;
        __syncthreads();
        if (threadIdx.x < 32) {
            float t = (threadIdx.x < TPB / 32) ? ws[threadIdx.x] : 0.0f;
            t = warp_reduce(t);
            if (threadIdx.x == 0) {
                out[0] = t / (float)B;
                g_counter = 0;                 // re-arm for next graph replay
            }
        }
    }
}

extern "C" void kernel_launch(void* const* d_in, const int* in_sizes, int n_in,
                              void* d_out, int out_size) {
    const float* logits = (const float*)d_in[0];
    const int*   y      = (const int*)d_in[1];
    const int    B      = in_sizes[1];

    const int nblocks = (B + TILE - 1) / TILE;     // 4096 for B = 4,194,304

    ordinal_loss_fused<<<nblocks, TPB>>>(logits, y, (float*)d_out, B, nblocks);
}